// round 12
// baseline (speedup 1.0000x reference)
#include <cuda_runtime.h>
#include <cuda_bf16.h>

// Problem constants
#define BB   32
#define TT   24
#define OO   128
#define HD   512
#define CTX  256
#define HOR  48
#define NB   (BB*OO)      // 4096 rows
#define RPB  32           // rows per block
#define NTH  256          // 8 warps: 2 row-groups(16 rows) x 4 unit-quarters
#define NBLK (NB/RPB)     // 128 CTAs
#define SZH  (RPB*HD)     // floats per h buffer

// SMEM layout (floats): h[2][32][512] | gtab[512][12] | stt[32][2] | aux[2048]
#define SM_GTAB   (2*SZH)
#define SM_STT    (SM_GTAB + HD*12)
#define SM_AUX    (SM_STT + RPB*2)
#define SM_FLOATS (SM_AUX + 2048)
#define SMEM_BYTES (SM_FLOATS*4)

typedef unsigned long long u64;

// ---------------- device scratch (no allocations allowed) ----------------
__device__ __align__(16) float scr_Whr_enc[512*3*512];   // [uu][g][i][lane][4]
__device__ __align__(16) float scr_Whr_cell[512*3*512];
__device__ __align__(16) float scr_W1r[512*512];          // [uu][i][lane][4]
__device__ __align__(16) float scr_GI_enc[512*12];        // per unit: m0r,m1r,cbr, m0z,m1z,cbz, m0n,m1n,cn, bhn, pad
__device__ __align__(16) float scr_GI_cell[512*12];
__device__ __align__(16) float scr_ctx[BB*HD];

// ---------------- packed fp32x2 helpers ----------------
__device__ __forceinline__ u64 ffma2(u64 a, u64 b, u64 c) {
    u64 d;
    asm("fma.rn.f32x2 %0, %1, %2, %3;" : "=l"(d) : "l"(a), "l"(b), "l"(c));
    return d;
}
__device__ __forceinline__ float f2sum(u64 v) {
    float lo, hi;
    asm("mov.b64 {%0,%1}, %2;" : "=f"(lo), "=f"(hi) : "l"(v));
    return lo + hi;
}

// ---------------- prep kernels ----------------

// Reorder Wh_enc / Wh_cell / W1 into warp-coalesced [uu][g][i][lane][4] layout.
__global__ void prep_reorder(const float* __restrict__ Whe,
                             const float* __restrict__ Whc,
                             const float* __restrict__ W1) {
    int i = blockIdx.x * blockDim.x + threadIdx.x;
    if (i < 512*3*512) {
        int c    = i & 3;
        int lane = (i >> 2) & 31;
        int ii   = (i >> 7) & 127;
        int t    = i >> 14;          // uu*3 + g
        int g    = t % 3;
        int uu   = t / 3;
        int jj   = uu * 32 + lane;
        int k    = ii * 4 + c;
        size_t src = (size_t)(g * 512 + jj) * 512 + k;
        scr_Whr_enc[i]  = Whe[src];
        scr_Whr_cell[i] = Whc[src];
    }
    if (i < 512*512) {
        int c    = i & 3;
        int lane = (i >> 2) & 31;
        int ii   = (i >> 7) & 127;
        int uu   = i >> 14;
        int jj   = uu * 32 + lane;
        int k    = ii * 4 + c;
        scr_W1r[i] = W1[(size_t)jj * 512 + k];
    }
}

// Fold W_emb/b_emb into the input projections: gi = x @ (Wi@W_emb).T + (Wi@b_emb + bi)
// Also fold bh into r/z biases; keep bh_n separate (multiplied by r gate).
__global__ void prep_gi(const float* __restrict__ Wi_enc, const float* __restrict__ bi_enc,
                        const float* __restrict__ bh_enc,
                        const float* __restrict__ Wi_cell, const float* __restrict__ bi_cell,
                        const float* __restrict__ bh_cell,
                        const float* __restrict__ W_emb, const float* __restrict__ b_emb) {
    int gwid = (blockIdx.x * blockDim.x + threadIdx.x) >> 5;
    int lane = threadIdx.x & 31;
    if (gwid >= 3072) return;
    int which = gwid / 1536;
    int rrow  = gwid % 1536;
    const float* Wi = which ? Wi_cell : Wi_enc;
    const float* bi = which ? bi_cell : bi_enc;
    const float* bh = which ? bh_cell : bh_enc;
    const float* wrow = Wi + (size_t)rrow * 512;
    float a0 = 0.f, a1 = 0.f, a2 = 0.f;
    for (int k = lane; k < 512; k += 32) {
        float w = wrow[k];
        a0 = fmaf(w, W_emb[2*k],   a0);
        a1 = fmaf(w, W_emb[2*k+1], a1);
        a2 = fmaf(w, b_emb[k],     a2);
    }
    for (int off = 16; off; off >>= 1) {
        a0 += __shfl_down_sync(0xffffffffu, a0, off);
        a1 += __shfl_down_sync(0xffffffffu, a1, off);
        a2 += __shfl_down_sync(0xffffffffu, a2, off);
    }
    if (lane == 0) {
        int g  = rrow >> 9;
        int jj = rrow & 511;
        float* G = (which ? scr_GI_cell : scr_GI_enc) + jj * 12;
        float c = a2 + bi[rrow];
        if (g == 0)      { G[0] = a0; G[1] = a1; G[2] = c + bh[rrow]; }
        else if (g == 1) { G[3] = a0; G[4] = a1; G[5] = c + bh[rrow]; }
        else             { G[6] = a0; G[7] = a1; G[8] = c; G[9] = bh[rrow]; }
    }
}

// ctx = z_ctx @ W_ctx.T + b_ctx   (32 x 512)
__global__ void prep_ctx(const float* __restrict__ z_ctx,
                         const float* __restrict__ W_ctx,
                         const float* __restrict__ b_ctx) {
    int idx = blockIdx.x * blockDim.x + threadIdx.x;
    if (idx >= BB * HD) return;
    int bb = idx >> 9;
    int j  = idx & 511;
    const float* z = z_ctx + bb * CTX;
    const float* w = W_ctx + (size_t)j * CTX;
    float a = 0.f;
    #pragma unroll 4
    for (int k = 0; k < CTX; k++) a = fmaf(z[k], w[k], a);
    scr_ctx[idx] = a + b_ctx[j];
}

// ---------------- fused GRU step ----------------
// 8 warps: rbase=(warp&1)*16 selects 16 rows, uq=warp>>1 selects 4 unit-groups.
// Each weight register now feeds 16 rows: per inner iter 3 LDG.128 (12 L1 wf)
// + 16 broadcast LDS (16 wf) amortized over 96 FFMA2.
__device__ __forceinline__ void gru_step(const float* __restrict__ hin,
                                         float* __restrict__ hout,
                                         const float* __restrict__ Wr,
                                         const float* __restrict__ gtab,
                                         const float* __restrict__ stt,
                                         int rbase, int lane, int uq) {
    const ulonglong2* __restrict__ hb = (const ulonglong2*)(hin + rbase * HD);
    for (int u = 0; u < 4; u++) {
        int uu = uq * 4 + u;
        int jj = uu * 32 + lane;
        const ulonglong2* __restrict__ wr = (const ulonglong2*)Wr + (size_t)(uu * 3) * 4096 + lane;
        const ulonglong2* __restrict__ wz = wr + 4096;
        const ulonglong2* __restrict__ wn = wz + 4096;
        u64 ar[16], az[16], an[16];
        #pragma unroll
        for (int r = 0; r < 16; r++) { ar[r] = 0ull; az[r] = 0ull; an[r] = 0ull; }
        #pragma unroll 2
        for (int i = 0; i < 128; i++) {
            ulonglong2 wa = wr[i * 32];
            ulonglong2 wb = wz[i * 32];
            ulonglong2 wc = wn[i * 32];
            #pragma unroll
            for (int r = 0; r < 16; r++) {
                ulonglong2 hv = hb[r * 128 + i];
                ar[r] = ffma2(hv.x, wa.x, ar[r]); ar[r] = ffma2(hv.y, wa.y, ar[r]);
                az[r] = ffma2(hv.x, wb.x, az[r]); az[r] = ffma2(hv.y, wb.y, az[r]);
                an[r] = ffma2(hv.x, wc.x, an[r]); an[r] = ffma2(hv.y, wc.y, an[r]);
            }
        }
        const float* gp = gtab + jj * 12;
        float m0r = gp[0], m1r = gp[1], cbr = gp[2];
        float m0z = gp[3], m1z = gp[4], cbz = gp[5];
        float m0n = gp[6], m1n = gp[7], cn  = gp[8], bhn = gp[9];
        #pragma unroll
        for (int r = 0; r < 16; r++) {
            int row = rbase + r;
            float x0 = stt[row * 2], x1 = stt[row * 2 + 1];
            float dr = f2sum(ar[r]) + fmaf(x1, m1r, fmaf(x0, m0r, cbr));
            float dz = f2sum(az[r]) + fmaf(x1, m1z, fmaf(x0, m0z, cbz));
            float dn = f2sum(an[r]);
            float rg = 1.f / (1.f + expf(-dr));
            float zg = 1.f / (1.f + expf(-dz));
            float ng = tanhf(fmaf(x1, m1n, fmaf(x0, m0n, cn)) + rg * (dn + bhn));
            float hp = hin[row * HD + jj];
            hout[row * HD + jj] = ng + zg * (hp - ng);
        }
    }
}

// ---------------- main persistent kernel ----------------
__global__ void __launch_bounds__(NTH, 1)
traj_main(const float* __restrict__ traj,
          const float* __restrict__ b1g,
          const float* __restrict__ W2g,
          const float* __restrict__ b2g,
          float* __restrict__ out) {
    extern __shared__ float sm[];
    float* hbuf = sm;
    float* gtab = sm + SM_GTAB;
    float* stt  = sm + SM_STT;
    float* aux  = sm + SM_AUX;

    int tid   = threadIdx.x;
    int lane  = tid & 31;
    int warp  = tid >> 5;
    int rbase = (warp & 1) * 16;  // 16 rows per warp
    int uq    = warp >> 1;        // unit quarter (4 unit-groups of 32 each)
    int gRow0 = blockIdx.x * RPB;
    int b     = gRow0 >> 7;       // all 32 rows in a CTA share the same batch index
    int o0    = gRow0 & 127;

    // init h = 0, load encoder gi table
    for (int i = tid; i < SZH; i += NTH) hbuf[i] = 0.f;
    for (int i = tid; i < HD * 12; i += NTH) gtab[i] = scr_GI_enc[i];
    __syncthreads();

    int cur = 0;
    // ---------------- encoder: 24 GRU steps ----------------
    for (int t = 0; t < TT; t++) {
        if (tid < RPB) {
            const float* p = traj + (((size_t)b * TT + t) * OO + o0 + tid) * 2;
            stt[tid * 2]     = p[0];
            stt[tid * 2 + 1] = p[1];
        }
        __syncthreads();
        gru_step(hbuf + cur * SZH, hbuf + (cur ^ 1) * SZH, scr_Whr_enc,
                 gtab, stt, rbase, lane, uq);
        cur ^= 1;
        __syncthreads();
    }

    // ---------------- h += ctx; state0; switch tables ----------------
    for (int i = tid; i < HD; i += NTH) aux[i] = scr_ctx[b * HD + i];
    __syncthreads();
    {
        float* hc = hbuf + cur * SZH;
        for (int i = tid; i < SZH; i += NTH) hc[i] += aux[i & (HD - 1)];
    }
    if (tid < RPB) {
        const float* p = traj + (((size_t)b * TT + (TT - 1)) * OO + o0 + tid) * 2;
        stt[tid * 2]     = p[0];
        stt[tid * 2 + 1] = p[1];
    }
    __syncthreads();
    for (int i = tid; i < HD * 12; i += NTH) gtab[i] = scr_GI_cell[i];
    for (int i = tid; i < HD; i += NTH)      aux[i] = b1g[i];
    for (int i = tid; i < 2 * HD; i += NTH)  aux[HD + i] = W2g[i];
    if (tid < 2) aux[3 * HD + tid] = b2g[tid];
    __syncthreads();

    // ---------------- decoder: 48 steps ----------------
    for (int s = 0; s < HOR; s++) {
        gru_step(hbuf + cur * SZH, hbuf + (cur ^ 1) * SZH, scr_Whr_cell,
                 gtab, stt, rbase, lane, uq);
        cur ^= 1;
        __syncthreads();

        const float* h  = hbuf + cur * SZH;
        float*      act = hbuf + (cur ^ 1) * SZH;

        // h1 = gelu(h @ W1.T + b1)
        const ulonglong2* __restrict__ hb = (const ulonglong2*)(h + rbase * HD);
        for (int u = 0; u < 4; u++) {
            int uu = uq * 4 + u;
            int jj = uu * 32 + lane;
            const ulonglong2* __restrict__ wp = (const ulonglong2*)scr_W1r + (size_t)uu * 4096 + lane;
            u64 a[16];
            #pragma unroll
            for (int r = 0; r < 16; r++) a[r] = 0ull;
            #pragma unroll 2
            for (int i = 0; i < 128; i++) {
                ulonglong2 w = wp[i * 32];
                #pragma unroll
                for (int r = 0; r < 16; r++) {
                    ulonglong2 hv = hb[r * 128 + i];
                    a[r] = ffma2(hv.x, w.x, a[r]);
                    a[r] = ffma2(hv.y, w.y, a[r]);
                }
            }
            float bb = aux[jj];
            #pragma unroll
            for (int r = 0; r < 16; r++) {
                float v = f2sum(a[r]) + bb;
                act[(rbase + r) * HD + jj] = 0.5f * v * (1.f + erff(v * 0.7071067811865475f));
            }
        }
        __syncthreads();

        // d = h1 @ W2.T + b2 ; clamp/step/wrap ; emit  (8 warps x 4 rows)
        #pragma unroll
        for (int r = 0; r < 4; r++) {
            int row = warp * 4 + r;
            const float* hr = act + row * HD;
            float s0 = 0.f, s1 = 0.f;
            #pragma unroll
            for (int k = lane; k < HD; k += 32) {
                float hv = hr[k];
                s0 = fmaf(hv, aux[HD + k],     s0);
                s1 = fmaf(hv, aux[2 * HD + k], s1);
            }
            #pragma unroll
            for (int off = 16; off; off >>= 1) {
                s0 += __shfl_down_sync(0xffffffffu, s0, off);
                s1 += __shfl_down_sync(0xffffffffu, s1, off);
            }
            if (lane == 0) {
                float d0 = s0 + aux[3 * HD];
                float d1 = s1 + aux[3 * HD + 1];
                d0 = 2.f * tanhf(d0 * 0.5f);
                d1 = 2.f * tanhf(d1 * 0.5f);
                float n0 = stt[row * 2]     + d0;
                float n1 = stt[row * 2 + 1] + d1;
                n0 = fminf(fmaxf(n0, -90.f), 90.f);
                float m = fmodf(n1, 360.f);
                if (m < 0.f) m += 360.f;
                stt[row * 2]     = n0;
                stt[row * 2 + 1] = m;
                size_t oo = (((size_t)b * HOR + s) * OO + (o0 + row)) * 2;
                out[oo]     = n0;
                out[oo + 1] = m;
            }
        }
        __syncthreads();
    }
}

// ---------------- launch ----------------
extern "C" void kernel_launch(void* const* d_in, const int* in_sizes, int n_in,
                              void* d_out, int out_size) {
    (void)in_sizes; (void)n_in; (void)out_size;
    const float* z_ctx   = (const float*)d_in[0];
    const float* traj    = (const float*)d_in[1];
    const float* W_emb   = (const float*)d_in[2];
    const float* b_emb   = (const float*)d_in[3];
    const float* W_ctx   = (const float*)d_in[4];
    const float* b_ctx   = (const float*)d_in[5];
    const float* Wi_enc  = (const float*)d_in[6];
    const float* Wh_enc  = (const float*)d_in[7];
    const float* bi_enc  = (const float*)d_in[8];
    const float* bh_enc  = (const float*)d_in[9];
    const float* Wi_cell = (const float*)d_in[10];
    const float* Wh_cell = (const float*)d_in[11];
    const float* bi_cell = (const float*)d_in[12];
    const float* bh_cell = (const float*)d_in[13];
    const float* W1      = (const float*)d_in[14];
    const float* b1      = (const float*)d_in[15];
    const float* W2      = (const float*)d_in[16];
    const float* b2      = (const float*)d_in[17];
    float* out = (float*)d_out;

    prep_reorder<<<3072, 256>>>(Wh_enc, Wh_cell, W1);
    prep_gi<<<384, 256>>>(Wi_enc, bi_enc, bh_enc, Wi_cell, bi_cell, bh_cell, W_emb, b_emb);
    prep_ctx<<<64, 256>>>(z_ctx, W_ctx, b_ctx);

    cudaFuncSetAttribute(traj_main, cudaFuncAttributeMaxDynamicSharedMemorySize, SMEM_BYTES);
    traj_main<<<NBLK, NTH, SMEM_BYTES>>>(traj, b1, W2, b2, out);
}

// round 13
// speedup vs baseline: 1.2494x; 1.2494x over previous
#include <cuda_runtime.h>
#include <cuda_bf16.h>

// Problem constants
#define BB   32
#define TT   24
#define OO   128
#define HD   512
#define CTX  256
#define HOR  48
#define NB   (BB*OO)      // 4096 rows
#define RPB  32           // rows per block
#define NTH  256          // 8 warps: 4 rowblocks(8 rows) x 2 unit-columns(256 units)
#define NBLK (NB/RPB)     // 128 CTAs
#define SZH  (RPB*HD)     // floats per h buffer

// SMEM layout (floats): h[2][32][512] | gtab[512][12] | stt[32][2] | aux[2048]
#define SM_GTAB   (2*SZH)
#define SM_STT    (SM_GTAB + HD*12)
#define SM_AUX    (SM_STT + RPB*2)
#define SM_FLOATS (SM_AUX + 2048)
#define SMEM_BYTES (SM_FLOATS*4)

typedef unsigned long long u64;

// ---------------- device scratch (no allocations allowed) ----------------
__device__ __align__(16) float scr_Whr_enc[512*3*512];   // [uu][g][i][lane][4]
__device__ __align__(16) float scr_Whr_cell[512*3*512];
__device__ __align__(16) float scr_W1r[512*512];          // [uu][i][lane][4]
__device__ __align__(16) float scr_GI_enc[512*12];
__device__ __align__(16) float scr_GI_cell[512*12];
__device__ __align__(16) float scr_ctx[BB*HD];

// ---------------- packed fp32x2 helpers ----------------
__device__ __forceinline__ u64 ffma2(u64 a, u64 b, u64 c) {
    u64 d;
    asm("fma.rn.f32x2 %0, %1, %2, %3;" : "=l"(d) : "l"(a), "l"(b), "l"(c));
    return d;
}
__device__ __forceinline__ float f2sum(u64 v) {
    float lo, hi;
    asm("mov.b64 {%0,%1}, %2;" : "=f"(lo), "=f"(hi) : "l"(v));
    return lo + hi;
}
__device__ __forceinline__ float sigmoid_fast(float x) {
    return 1.f / (1.f + __expf(-x));
}
__device__ __forceinline__ float tanh_fast(float x) {
    float y;
    asm("tanh.approx.f32 %0, %1;" : "=f"(y) : "f"(x));
    return y;
}

// ---------------- prep kernels ----------------

// Reorder Wh_enc / Wh_cell / W1 into warp-coalesced [uu][g][i][lane][4] layout.
__global__ void prep_reorder(const float* __restrict__ Whe,
                             const float* __restrict__ Whc,
                             const float* __restrict__ W1) {
    int i = blockIdx.x * blockDim.x + threadIdx.x;
    if (i < 512*3*512) {
        int c    = i & 3;
        int lane = (i >> 2) & 31;
        int ii   = (i >> 7) & 127;
        int t    = i >> 14;          // uu*3 + g
        int g    = t % 3;
        int uu   = t / 3;
        int jj   = uu * 32 + lane;
        int k    = ii * 4 + c;
        size_t src = (size_t)(g * 512 + jj) * 512 + k;
        scr_Whr_enc[i]  = Whe[src];
        scr_Whr_cell[i] = Whc[src];
    }
    if (i < 512*512) {
        int c    = i & 3;
        int lane = (i >> 2) & 31;
        int ii   = (i >> 7) & 127;
        int uu   = i >> 14;
        int jj   = uu * 32 + lane;
        int k    = ii * 4 + c;
        scr_W1r[i] = W1[(size_t)jj * 512 + k];
    }
}

// Fold W_emb/b_emb into the input projections: gi = x @ (Wi@W_emb).T + (Wi@b_emb + bi)
__global__ void prep_gi(const float* __restrict__ Wi_enc, const float* __restrict__ bi_enc,
                        const float* __restrict__ bh_enc,
                        const float* __restrict__ Wi_cell, const float* __restrict__ bi_cell,
                        const float* __restrict__ bh_cell,
                        const float* __restrict__ W_emb, const float* __restrict__ b_emb) {
    int gwid = (blockIdx.x * blockDim.x + threadIdx.x) >> 5;
    int lane = threadIdx.x & 31;
    if (gwid >= 3072) return;
    int which = gwid / 1536;
    int rrow  = gwid % 1536;
    const float* Wi = which ? Wi_cell : Wi_enc;
    const float* bi = which ? bi_cell : bi_enc;
    const float* bh = which ? bh_cell : bh_enc;
    const float* wrow = Wi + (size_t)rrow * 512;
    float a0 = 0.f, a1 = 0.f, a2 = 0.f;
    for (int k = lane; k < 512; k += 32) {
        float w = wrow[k];
        a0 = fmaf(w, W_emb[2*k],   a0);
        a1 = fmaf(w, W_emb[2*k+1], a1);
        a2 = fmaf(w, b_emb[k],     a2);
    }
    for (int off = 16; off; off >>= 1) {
        a0 += __shfl_down_sync(0xffffffffu, a0, off);
        a1 += __shfl_down_sync(0xffffffffu, a1, off);
        a2 += __shfl_down_sync(0xffffffffu, a2, off);
    }
    if (lane == 0) {
        int g  = rrow >> 9;
        int jj = rrow & 511;
        float* G = (which ? scr_GI_cell : scr_GI_enc) + jj * 12;
        float c = a2 + bi[rrow];
        if (g == 0)      { G[0] = a0; G[1] = a1; G[2] = c + bh[rrow]; }
        else if (g == 1) { G[3] = a0; G[4] = a1; G[5] = c + bh[rrow]; }
        else             { G[6] = a0; G[7] = a1; G[8] = c; G[9] = bh[rrow]; }
    }
}

// ctx = z_ctx @ W_ctx.T + b_ctx   (32 x 512)
__global__ void prep_ctx(const float* __restrict__ z_ctx,
                         const float* __restrict__ W_ctx,
                         const float* __restrict__ b_ctx) {
    int idx = blockIdx.x * blockDim.x + threadIdx.x;
    if (idx >= BB * HD) return;
    int bb = idx >> 9;
    int j  = idx & 511;
    const float* z = z_ctx + bb * CTX;
    const float* w = W_ctx + (size_t)j * CTX;
    float a = 0.f;
    #pragma unroll 4
    for (int k = 0; k < CTX; k++) a = fmaf(z[k], w[k], a);
    scr_ctx[idx] = a + b_ctx[j];
}

// ---------------- fused GRU step ----------------
// 8 warps = 4 rowblocks (8 rows each) x 2 unit-columns (256 units each).
// Per warp: outer loop of 4 over pairs of 32-unit groups (u_in=2).
// Inner iter: 8 broadcast LDS (h) + 6 LDG.128 (weights) feed 96 FFMA2 —
// smem-return cost per FFMA2 drops 0.79 -> 0.58 vs previous layout.
__device__ __forceinline__ void gru_step(const float* __restrict__ hin,
                                         float* __restrict__ hout,
                                         const float* __restrict__ Wr,
                                         const float* __restrict__ gtab,
                                         const float* __restrict__ stt,
                                         int rbase, int lane, int ucol) {
    const ulonglong2* __restrict__ hb = (const ulonglong2*)(hin + rbase * HD);
    #pragma unroll 1
    for (int uo = 0; uo < 4; uo++) {
        int ugA = ucol * 8 + uo * 2;
        const ulonglong2* __restrict__ w0 = (const ulonglong2*)Wr + (size_t)(ugA * 3) * 4096 + lane;
        const ulonglong2* __restrict__ w1 = (const ulonglong2*)Wr + (size_t)((ugA + 1) * 3) * 4096 + lane;
        u64 a0r[8], a0z[8], a0n[8], a1r[8], a1z[8], a1n[8];
        #pragma unroll
        for (int r = 0; r < 8; r++) {
            a0r[r] = 0ull; a0z[r] = 0ull; a0n[r] = 0ull;
            a1r[r] = 0ull; a1z[r] = 0ull; a1n[r] = 0ull;
        }
        #pragma unroll 2
        for (int i = 0; i < 128; i++) {
            ulonglong2 v0r = w0[i * 32];
            ulonglong2 v0z = w0[4096 + i * 32];
            ulonglong2 v0n = w0[8192 + i * 32];
            ulonglong2 v1r = w1[i * 32];
            ulonglong2 v1z = w1[4096 + i * 32];
            ulonglong2 v1n = w1[8192 + i * 32];
            #pragma unroll
            for (int r = 0; r < 8; r++) {
                ulonglong2 hv = hb[r * 128 + i];
                a0r[r] = ffma2(hv.x, v0r.x, a0r[r]); a0r[r] = ffma2(hv.y, v0r.y, a0r[r]);
                a0z[r] = ffma2(hv.x, v0z.x, a0z[r]); a0z[r] = ffma2(hv.y, v0z.y, a0z[r]);
                a0n[r] = ffma2(hv.x, v0n.x, a0n[r]); a0n[r] = ffma2(hv.y, v0n.y, a0n[r]);
                a1r[r] = ffma2(hv.x, v1r.x, a1r[r]); a1r[r] = ffma2(hv.y, v1r.y, a1r[r]);
                a1z[r] = ffma2(hv.x, v1z.x, a1z[r]); a1z[r] = ffma2(hv.y, v1z.y, a1z[r]);
                a1n[r] = ffma2(hv.x, v1n.x, a1n[r]); a1n[r] = ffma2(hv.y, v1n.y, a1n[r]);
            }
        }
        #pragma unroll
        for (int g = 0; g < 2; g++) {
            int jj = (ugA + g) * 32 + lane;
            const float* gp = gtab + jj * 12;
            float m0r = gp[0], m1r = gp[1], cbr = gp[2];
            float m0z = gp[3], m1z = gp[4], cbz = gp[5];
            float m0n = gp[6], m1n = gp[7], cn  = gp[8], bhn = gp[9];
            #pragma unroll
            for (int r = 0; r < 8; r++) {
                int row = rbase + r;
                float x0 = stt[row * 2], x1 = stt[row * 2 + 1];
                float dr = f2sum(g ? a1r[r] : a0r[r]) + fmaf(x1, m1r, fmaf(x0, m0r, cbr));
                float dz = f2sum(g ? a1z[r] : a0z[r]) + fmaf(x1, m1z, fmaf(x0, m0z, cbz));
                float dn = f2sum(g ? a1n[r] : a0n[r]);
                float rg = sigmoid_fast(dr);
                float zg = sigmoid_fast(dz);
                float ng = tanh_fast(fmaf(x1, m1n, fmaf(x0, m0n, cn)) + rg * (dn + bhn));
                float hp = hin[row * HD + jj];
                hout[row * HD + jj] = ng + zg * (hp - ng);
            }
        }
    }
}

// ---------------- main persistent kernel ----------------
__global__ void __launch_bounds__(NTH, 1)
traj_main(const float* __restrict__ traj,
          const float* __restrict__ b1g,
          const float* __restrict__ W2g,
          const float* __restrict__ b2g,
          float* __restrict__ out) {
    extern __shared__ float sm[];
    float* hbuf = sm;
    float* gtab = sm + SM_GTAB;
    float* stt  = sm + SM_STT;
    float* aux  = sm + SM_AUX;

    int tid   = threadIdx.x;
    int lane  = tid & 31;
    int warp  = tid >> 5;
    int rbase = (warp & 3) * 8;  // 4 rowblocks of 8 rows
    int ucol  = warp >> 2;       // 2 unit-columns of 256 units
    int gRow0 = blockIdx.x * RPB;
    int b     = gRow0 >> 7;
    int o0    = gRow0 & 127;

    // init h = 0, load encoder gi table
    for (int i = tid; i < SZH; i += NTH) hbuf[i] = 0.f;
    for (int i = tid; i < HD * 12; i += NTH) gtab[i] = scr_GI_enc[i];
    __syncthreads();

    int cur = 0;
    // ---------------- encoder: 24 GRU steps ----------------
    for (int t = 0; t < TT; t++) {
        if (tid < RPB) {
            const float* p = traj + (((size_t)b * TT + t) * OO + o0 + tid) * 2;
            stt[tid * 2]     = p[0];
            stt[tid * 2 + 1] = p[1];
        }
        __syncthreads();
        gru_step(hbuf + cur * SZH, hbuf + (cur ^ 1) * SZH, scr_Whr_enc,
                 gtab, stt, rbase, lane, ucol);
        cur ^= 1;
        __syncthreads();
    }

    // ---------------- h += ctx; state0; switch tables ----------------
    for (int i = tid; i < HD; i += NTH) aux[i] = scr_ctx[b * HD + i];
    __syncthreads();
    {
        float* hc = hbuf + cur * SZH;
        for (int i = tid; i < SZH; i += NTH) hc[i] += aux[i & (HD - 1)];
    }
    if (tid < RPB) {
        const float* p = traj + (((size_t)b * TT + (TT - 1)) * OO + o0 + tid) * 2;
        stt[tid * 2]     = p[0];
        stt[tid * 2 + 1] = p[1];
    }
    __syncthreads();
    for (int i = tid; i < HD * 12; i += NTH) gtab[i] = scr_GI_cell[i];
    for (int i = tid; i < HD; i += NTH)      aux[i] = b1g[i];
    for (int i = tid; i < 2 * HD; i += NTH)  aux[HD + i] = W2g[i];
    if (tid < 2) aux[3 * HD + tid] = b2g[tid];
    __syncthreads();

    // ---------------- decoder: 48 steps ----------------
    for (int s = 0; s < HOR; s++) {
        gru_step(hbuf + cur * SZH, hbuf + (cur ^ 1) * SZH, scr_Whr_cell,
                 gtab, stt, rbase, lane, ucol);
        cur ^= 1;
        __syncthreads();

        const float* h  = hbuf + cur * SZH;
        float*      act = hbuf + (cur ^ 1) * SZH;

        // h1 = gelu(h @ W1.T + b1): per warp 8 rows x 8 ug, u_in=4
        const ulonglong2* __restrict__ hb = (const ulonglong2*)(h + rbase * HD);
        #pragma unroll 1
        for (int uo = 0; uo < 2; uo++) {
            int ugA = ucol * 8 + uo * 4;
            const ulonglong2* __restrict__ wp0 = (const ulonglong2*)scr_W1r + (size_t)(ugA + 0) * 4096 + lane;
            const ulonglong2* __restrict__ wp1 = (const ulonglong2*)scr_W1r + (size_t)(ugA + 1) * 4096 + lane;
            const ulonglong2* __restrict__ wp2 = (const ulonglong2*)scr_W1r + (size_t)(ugA + 2) * 4096 + lane;
            const ulonglong2* __restrict__ wp3 = (const ulonglong2*)scr_W1r + (size_t)(ugA + 3) * 4096 + lane;
            u64 a0[8], a1[8], a2[8], a3[8];
            #pragma unroll
            for (int r = 0; r < 8; r++) { a0[r] = 0ull; a1[r] = 0ull; a2[r] = 0ull; a3[r] = 0ull; }
            #pragma unroll 2
            for (int i = 0; i < 128; i++) {
                ulonglong2 w0 = wp0[i * 32];
                ulonglong2 w1 = wp1[i * 32];
                ulonglong2 w2 = wp2[i * 32];
                ulonglong2 w3 = wp3[i * 32];
                #pragma unroll
                for (int r = 0; r < 8; r++) {
                    ulonglong2 hv = hb[r * 128 + i];
                    a0[r] = ffma2(hv.x, w0.x, a0[r]); a0[r] = ffma2(hv.y, w0.y, a0[r]);
                    a1[r] = ffma2(hv.x, w1.x, a1[r]); a1[r] = ffma2(hv.y, w1.y, a1[r]);
                    a2[r] = ffma2(hv.x, w2.x, a2[r]); a2[r] = ffma2(hv.y, w2.y, a2[r]);
                    a3[r] = ffma2(hv.x, w3.x, a3[r]); a3[r] = ffma2(hv.y, w3.y, a3[r]);
                }
            }
            #pragma unroll
            for (int g = 0; g < 4; g++) {
                int jj = (ugA + g) * 32 + lane;
                float bb = aux[jj];
                #pragma unroll
                for (int r = 0; r < 8; r++) {
                    u64 av = (g == 0) ? a0[r] : (g == 1) ? a1[r] : (g == 2) ? a2[r] : a3[r];
                    float v = f2sum(av) + bb;
                    act[(rbase + r) * HD + jj] = 0.5f * v * (1.f + erff(v * 0.7071067811865475f));
                }
            }
        }
        __syncthreads();

        // d = h1 @ W2.T + b2 ; clamp/step/wrap ; emit  (8 warps x 4 rows)
        #pragma unroll
        for (int r = 0; r < 4; r++) {
            int row = warp * 4 + r;
            const float* hr = act + row * HD;
            float s0 = 0.f, s1 = 0.f;
            #pragma unroll
            for (int k = lane; k < HD; k += 32) {
                float hv = hr[k];
                s0 = fmaf(hv, aux[HD + k],     s0);
                s1 = fmaf(hv, aux[2 * HD + k], s1);
            }
            #pragma unroll
            for (int off = 16; off; off >>= 1) {
                s0 += __shfl_down_sync(0xffffffffu, s0, off);
                s1 += __shfl_down_sync(0xffffffffu, s1, off);
            }
            if (lane == 0) {
                float d0 = s0 + aux[3 * HD];
                float d1 = s1 + aux[3 * HD + 1];
                d0 = 2.f * tanhf(d0 * 0.5f);
                d1 = 2.f * tanhf(d1 * 0.5f);
                float n0 = stt[row * 2]     + d0;
                float n1 = stt[row * 2 + 1] + d1;
                n0 = fminf(fmaxf(n0, -90.f), 90.f);
                float m = fmodf(n1, 360.f);
                if (m < 0.f) m += 360.f;
                stt[row * 2]     = n0;
                stt[row * 2 + 1] = m;
                size_t oo = (((size_t)b * HOR + s) * OO + (o0 + row)) * 2;
                out[oo]     = n0;
                out[oo + 1] = m;
            }
        }
        __syncthreads();
    }
}

// ---------------- launch ----------------
extern "C" void kernel_launch(void* const* d_in, const int* in_sizes, int n_in,
                              void* d_out, int out_size) {
    (void)in_sizes; (void)n_in; (void)out_size;
    const float* z_ctx   = (const float*)d_in[0];
    const float* traj    = (const float*)d_in[1];
    const float* W_emb   = (const float*)d_in[2];
    const float* b_emb   = (const float*)d_in[3];
    const float* W_ctx   = (const float*)d_in[4];
    const float* b_ctx   = (const float*)d_in[5];
    const float* Wi_enc  = (const float*)d_in[6];
    const float* Wh_enc  = (const float*)d_in[7];
    const float* bi_enc  = (const float*)d_in[8];
    const float* bh_enc  = (const float*)d_in[9];
    const float* Wi_cell = (const float*)d_in[10];
    const float* Wh_cell = (const float*)d_in[11];
    const float* bi_cell = (const float*)d_in[12];
    const float* bh_cell = (const float*)d_in[13];
    const float* W1      = (const float*)d_in[14];
    const float* b1      = (const float*)d_in[15];
    const float* W2      = (const float*)d_in[16];
    const float* b2      = (const float*)d_in[17];
    float* out = (float*)d_out;

    prep_reorder<<<3072, 256>>>(Wh_enc, Wh_cell, W1);
    prep_gi<<<384, 256>>>(Wi_enc, bi_enc, bh_enc, Wi_cell, bi_cell, bh_cell, W_emb, b_emb);
    prep_ctx<<<64, 256>>>(z_ctx, W_ctx, b_ctx);

    cudaFuncSetAttribute(traj_main, cudaFuncAttributeMaxDynamicSharedMemorySize, SMEM_BYTES);
    traj_main<<<NBLK, NTH, SMEM_BYTES>>>(traj, b1, W2, b2, out);
}